// round 1
// baseline (speedup 1.0000x reference)
#include <cuda_runtime.h>
#include <math.h>
#include <stdint.h>

#define NPOS 2500
#define NANCH 22500
#define SORTN 32768
#define PRE 6000
#define POST 300

// ---------------- scratch (device globals: no allocation allowed) ----------------
__device__ float g_feat[512 * NPOS];               // conv3x3 + leaky output, [512][2500]
__device__ float g_P[54 * NPOS];                   // head GEMM output, [54][2500]
__device__ float4 g_boxes[NANCH];                  // clipped candidate boxes
__device__ unsigned long long g_key[SORTN];        // sort keys

// ---------------- conv 3x3 (batch 7 only) as implicit GEMM ----------------
// out[m, n] = sum_k W[m, k] * B[k, n],  k = ci*9 + kh*3 + kw, n = h*50 + w
// BM=128, BN=64, BK=16, 256 threads, thread tile 8x4
__global__ __launch_bounds__(256) void conv3_kernel(const float* __restrict__ in,
                                                    const float* __restrict__ w,
                                                    const float* __restrict__ bias) {
    __shared__ float As[16][128];
    __shared__ float Bs[16][64];
    const int bn = blockIdx.x * 64;
    const int bm = blockIdx.y * 128;
    const int tid = threadIdx.x;

    float acc[8][4];
#pragma unroll
    for (int i = 0; i < 8; i++)
#pragma unroll
        for (int j = 0; j < 4; j++) acc[i][j] = 0.f;

    const int tm = tid >> 4;   // 0..15
    const int tn = tid & 15;   // 0..15

    for (int k0 = 0; k0 < 4608; k0 += 16) {
        // A tile: 128 rows x 16 k  (weights are already row-major [512][4608])
#pragma unroll
        for (int q = 0; q < 2; q++) {
            int f4i = tid * 2 + q;           // 0..511
            int m = f4i >> 2;                // 0..127
            int kq = (f4i & 3) * 4;          // 0,4,8,12
            float4 v = *(const float4*)&w[(size_t)(bm + m) * 4608 + k0 + kq];
            As[kq + 0][m] = v.x;
            As[kq + 1][m] = v.y;
            As[kq + 2][m] = v.z;
            As[kq + 3][m] = v.w;
        }
        // B tile: implicit im2col gather, 16 k x 64 n
#pragma unroll
        for (int q = 0; q < 4; q++) {
            int idx = tid + 256 * q;
            int kl = idx >> 6;               // 0..15
            int nl = idx & 63;
            int k = k0 + kl;
            int n = bn + nl;
            float v = 0.f;
            if (n < NPOS) {
                int ci = k / 9;
                int r = k - ci * 9;
                int kh = r / 3;
                int kw = r - kh * 3;
                int h = n / 50;
                int ww = n - h * 50;
                int ih = h + kh - 1;
                int iw = ww + kw - 1;
                if (ih >= 0 && ih < 50 && iw >= 0 && iw < 50)
                    v = in[(size_t)ci * NPOS + ih * 50 + iw];
            }
            Bs[kl][nl] = v;
        }
        __syncthreads();
#pragma unroll
        for (int kk = 0; kk < 16; kk++) {
            float a[8], b[4];
            *(float4*)&a[0] = *(float4*)&As[kk][tm * 8];
            *(float4*)&a[4] = *(float4*)&As[kk][tm * 8 + 4];
            *(float4*)&b[0] = *(float4*)&Bs[kk][tn * 4];
#pragma unroll
            for (int i = 0; i < 8; i++)
#pragma unroll
                for (int j = 0; j < 4; j++) acc[i][j] += a[i] * b[j];
        }
        __syncthreads();
    }

#pragma unroll
    for (int i = 0; i < 8; i++) {
        int m = bm + tm * 8 + i;
        float bv = bias[m];
#pragma unroll
        for (int j = 0; j < 4; j++) {
            int n = bn + tn * 4 + j;
            if (n < NPOS) {
                float v = acc[i][j] + bv;
                g_feat[(size_t)m * NPOS + n] = (v >= 0.f) ? v : 0.01f * v;
            }
        }
    }
}

// ---------------- head GEMM: [54][512] x feat[512][2500] -> g_P ----------------
// rows 0..35 = reg_w, rows 36..53 = cls_w. BM=64, BN=64, BK=16, 256 thr, 4x4.
__global__ __launch_bounds__(256) void head_kernel(const float* __restrict__ reg_w,
                                                   const float* __restrict__ cls_w) {
    __shared__ float As[16][64];
    __shared__ float Bs[16][64];
    const int bn = blockIdx.x * 64;
    const int t = threadIdx.x;
    float acc[4][4];
#pragma unroll
    for (int i = 0; i < 4; i++)
#pragma unroll
        for (int j = 0; j < 4; j++) acc[i][j] = 0.f;

    const int tm = t >> 4, tn = t & 15;

    for (int k0 = 0; k0 < 512; k0 += 16) {
        {
            int m = t >> 2;
            int kq = (t & 3) * 4;
            float4 v = make_float4(0.f, 0.f, 0.f, 0.f);
            if (m < 36) v = *(const float4*)&reg_w[m * 512 + k0 + kq];
            else if (m < 54) v = *(const float4*)&cls_w[(m - 36) * 512 + k0 + kq];
            As[kq + 0][m] = v.x;
            As[kq + 1][m] = v.y;
            As[kq + 2][m] = v.z;
            As[kq + 3][m] = v.w;
        }
        {
            int kl = t >> 4;
            int nq = (t & 15) * 4;
            int n = bn + nq;
            float4 v = make_float4(0.f, 0.f, 0.f, 0.f);
            if (n + 3 < NPOS) {
                v = *(const float4*)&g_feat[(size_t)(k0 + kl) * NPOS + n];
            } else {
                float tmp[4] = {0.f, 0.f, 0.f, 0.f};
                for (int q = 0; q < 4; q++)
                    if (n + q < NPOS) tmp[q] = g_feat[(size_t)(k0 + kl) * NPOS + n + q];
                v = make_float4(tmp[0], tmp[1], tmp[2], tmp[3]);
            }
            *(float4*)&Bs[kl][nq] = v;
        }
        __syncthreads();
#pragma unroll
        for (int kk = 0; kk < 16; kk++) {
            float a[4], b[4];
            *(float4*)&a[0] = *(float4*)&As[kk][tm * 4];
            *(float4*)&b[0] = *(float4*)&Bs[kk][tn * 4];
#pragma unroll
            for (int i = 0; i < 4; i++)
#pragma unroll
                for (int j = 0; j < 4; j++) acc[i][j] += a[i] * b[j];
        }
        __syncthreads();
    }
#pragma unroll
    for (int i = 0; i < 4; i++) {
        int m = tm * 4 + i;
        if (m < 54) {
#pragma unroll
            for (int j = 0; j < 4; j++) {
                int n = bn + tn * 4 + j;
                if (n < NPOS) g_P[(size_t)m * NPOS + n] = acc[i][j];
            }
        }
    }
}

// ---------------- decode: boxes + sort keys ----------------
__global__ __launch_bounds__(256) void decode_kernel(const float* __restrict__ reg_b,
                                                     const float* __restrict__ cls_b) {
    int t = blockIdx.x * 256 + threadIdx.x;
    if (t >= SORTN) return;
    if (t >= NANCH) {
        g_key[t] = 0xFFFFFFFFFFFFFFFFull;
        return;
    }
    int pos = t / 9;
    int a = t - pos * 9;
    int h = pos / 50;
    int w = pos - h * 50;

    float pr0 = g_P[(4 * a + 0) * NPOS + pos] + reg_b[4 * a + 0];
    float pr1 = g_P[(4 * a + 1) * NPOS + pos] + reg_b[4 * a + 1];
    float pr2 = g_P[(4 * a + 2) * NPOS + pos] + reg_b[4 * a + 2];
    float pr3 = g_P[(4 * a + 3) * NPOS + pos] + reg_b[4 * a + 3];
    float l0 = g_P[(36 + 2 * a + 0) * NPOS + pos] + cls_b[2 * a + 0];
    float l1 = g_P[(36 + 2 * a + 1) * NPOS + pos] + cls_b[2 * a + 1];

    // softmax score, exactly as jax.nn.softmax (sub max, exp, /sum)
    float mx = fmaxf(l0, l1);
    float e0 = expf(l0 - mx);
    float e1 = expf(l1 - mx);
    float score = e1 / (e0 + e1);

    // anchors (a = ri*3 + si; ri over ratios, si over scales)
    const float rs_[3] = {0.5f, 1.0f, 2.0f};
    const float ss_[3] = {8.0f, 16.0f, 32.0f};
    int ri = a / 3;
    int si = a - ri * 3;
    float hs = (16.0f * ss_[si]) * sqrtf(rs_[ri]);
    float ws = (16.0f * ss_[si]) * sqrtf(1.0f / rs_[ri]);
    float cx = 16.0f * (float)h + 8.0f;   // cx = repeat(c, FS) -> indexed by h
    float cy = 16.0f * (float)w + 8.0f;
    float ax1 = cx - ws * 0.5f;
    float ay1 = cy - hs * 0.5f;

    const float hi = 799.0f;
    float rx1 = fminf(fmaxf(pr0 + ax1, 0.f), hi);
    float ry1 = fminf(fmaxf(pr1 + ay1, 0.f), hi);
    float rx2 = fminf(fmaxf(pr0 + ax1 + pr2 + ws, 0.f), hi);
    float ry2 = fminf(fmaxf(pr1 + ay1 + pr3 + hs, 0.f), hi);

    float wv = pr2 + ws;
    float hv = pr3 + hs;
    bool valid = (wv >= 16.0f) && (hv >= 16.0f);
    float s = valid ? score : -INFINITY;

    g_boxes[t] = make_float4(rx1, ry1, rx2, ry2);

    unsigned u = __float_as_uint(s);
    u = (u & 0x80000000u) ? ~u : (u | 0x80000000u);  // ascending-order uint map
    unsigned du = ~u;                                // descending score key
    g_key[t] = ((unsigned long long)du << 32) | (unsigned)t;
}

// ---------------- bitonic sort (ascending u64) ----------------
__device__ __forceinline__ void cmpswap_u64(unsigned long long* a, unsigned long long* b, bool up) {
    unsigned long long x = *a, y = *b;
    bool sw = up ? (x > y) : (x < y);
    if (sw) { *a = y; *b = x; }
}

__global__ __launch_bounds__(1024) void sort_local_kernel() {
    __shared__ unsigned long long s[2048];
    int base = blockIdx.x * 2048;
    int t = threadIdx.x;
    s[t] = g_key[base + t];
    s[t + 1024] = g_key[base + t + 1024];
    __syncthreads();
    for (int k = 2; k <= 2048; k <<= 1) {
        for (int j = k >> 1; j > 0; j >>= 1) {
            int i = ((t & ~(j - 1)) << 1) | (t & (j - 1));
            int p = i | j;
            bool up = (((base + i) & k) == 0);
            cmpswap_u64(&s[i], &s[p], up);
            __syncthreads();
        }
    }
    g_key[base + t] = s[t];
    g_key[base + t + 1024] = s[t + 1024];
}

__global__ __launch_bounds__(1024) void sort_pass_kernel(int k, int j) {
    int t = blockIdx.x * 1024 + threadIdx.x;   // 16384 threads
    int i = ((t & ~(j - 1)) << 1) | (t & (j - 1));
    int p = i + j;
    bool up = ((i & k) == 0);
    unsigned long long a = g_key[i], b = g_key[p];
    bool sw = up ? (a > b) : (a < b);
    if (sw) { g_key[i] = b; g_key[p] = a; }
}

__global__ __launch_bounds__(1024) void sort_low_kernel(int k) {
    __shared__ unsigned long long s[2048];
    int base = blockIdx.x * 2048;
    int t = threadIdx.x;
    s[t] = g_key[base + t];
    s[t + 1024] = g_key[base + t + 1024];
    __syncthreads();
    for (int j = 1024; j > 0; j >>= 1) {
        int i = ((t & ~(j - 1)) << 1) | (t & (j - 1));
        int p = i | j;
        bool up = (((base + i) & k) == 0);
        cmpswap_u64(&s[i], &s[p], up);
        __syncthreads();
    }
    g_key[base + t] = s[t];
    g_key[base + t + 1024] = s[t + 1024];
}

// ---------------- NMS + final select (single block) ----------------
extern __shared__ float nms_smem[];
__global__ __launch_bounds__(1024) void nms_kernel(float* __restrict__ out) {
    float* X1 = nms_smem;
    float* Y1 = X1 + PRE;
    float* X2 = Y1 + PRE;
    float* Y2 = X2 + PRE;
    float* AR = Y2 + PRE;
    unsigned char* keep = (unsigned char*)(AR + PRE);          // PRE bytes
    int* sel = (int*)((char*)nms_smem + 5 * PRE * 4 + 6000);   // 300 ints

    __shared__ int s_cur, s_cnt;
    const int t = threadIdx.x;

    for (int r = t; r < PRE; r += 1024) {
        int idx = (int)(g_key[r] & 0xFFFFFFFFull);
        float4 b = g_boxes[idx];
        X1[r] = b.x; Y1[r] = b.y; X2[r] = b.z; Y2[r] = b.w;
        AR[r] = (b.z - b.x + 1.0f) * (b.w - b.y + 1.0f);
        keep[r] = 1;
    }
    if (t == 0) s_cnt = 0;
    __syncthreads();

    int i_scan = 0;  // valid only on thread 0
    while (true) {
        if (t == 0) {
            int i = i_scan;
            while (i < PRE && !keep[i]) i++;
            if (i < PRE && s_cnt < POST) {
                sel[s_cnt] = i;
                s_cnt++;
                s_cur = i;
                i_scan = i + 1;
            } else {
                s_cur = -1;
            }
        }
        __syncthreads();
        int cur = s_cur;
        if (cur < 0) break;
        float x1i = X1[cur], y1i = Y1[cur], x2i = X2[cur], y2i = Y2[cur], ai = AR[cur];
        for (int j = cur + 1 + t; j < PRE; j += 1024) {
            float xx1 = fmaxf(x1i, X1[j]);
            float yy1 = fmaxf(y1i, Y1[j]);
            float xx2 = fminf(x2i, X2[j]);
            float yy2 = fmaxf(y2i, Y2[j]);   // reference's maximum bug preserved
            float w = fmaxf(0.f, xx2 - xx1 + 1.0f);
            float h = fmaxf(0.f, yy2 - yy1 + 1.0f);
            float inter = w * h;
            float ov = inter / (ai + AR[j] - inter);
            if (ov > 0.7f) keep[j] = 0;
        }
        __syncthreads();
    }

    // pad with suppressed indices (ascending) if fewer than 300 kept
    if (t == 0) {
        int c = s_cnt;
        for (int i = 0; i < PRE && c < POST; i++)
            if (!keep[i]) sel[c++] = i;
        s_cnt = c;
    }
    __syncthreads();

    if (t < POST) {
        int idx = sel[t];
        out[t * 4 + 0] = X1[idx];
        out[t * 4 + 1] = Y1[idx];
        out[t * 4 + 2] = X2[idx] - X1[idx] + 1.0f;
        out[t * 4 + 3] = Y2[idx] - Y1[idx] + 1.0f;
    }
}

// ---------------- launch ----------------
extern "C" void kernel_launch(void* const* d_in, const int* in_sizes, int n_in,
                              void* d_out, int out_size) {
    const float* in_features = (const float*)d_in[0];
    const float* conv_w = (const float*)d_in[1];
    const float* conv_b = (const float*)d_in[2];
    const float* reg_w = (const float*)d_in[3];
    const float* reg_b = (const float*)d_in[4];
    const float* cls_w = (const float*)d_in[5];
    const float* cls_b = (const float*)d_in[6];
    float* out = (float*)d_out;

    const float* in7 = in_features + (size_t)7 * 512 * NPOS;  // only batch -1 is consumed

    // conv3x3 + bias + leaky (batch 7 only)
    conv3_kernel<<<dim3(40, 4), 256>>>(in7, conv_w, conv_b);

    // reg/cls 1x1 heads as one GEMM
    head_kernel<<<40, 256>>>(reg_w, cls_w);

    // box decode + softmax score + sort keys
    decode_kernel<<<128, 256>>>(reg_b, cls_b);

    // bitonic sort of 32768 keys
    sort_local_kernel<<<16, 1024>>>();
    for (int k = 4096; k <= 32768; k <<= 1) {
        for (int j = k >> 1; j >= 2048; j >>= 1)
            sort_pass_kernel<<<16, 1024>>>(k, j);
        sort_low_kernel<<<16, 1024>>>(k);
    }

    // NMS + output
    const int nms_smem_bytes = 5 * PRE * 4 + 6000 + POST * 4 + 32;
    cudaFuncSetAttribute(nms_kernel, cudaFuncAttributeMaxDynamicSharedMemorySize, nms_smem_bytes);
    nms_kernel<<<1, 1024, nms_smem_bytes>>>(out);
}

// round 2
// speedup vs baseline: 1.2380x; 1.2380x over previous
#include <cuda_runtime.h>
#include <math.h>
#include <stdint.h>

#define NPOS 2500
#define NPAD 2560
#define NANCH 22500
#define PRE 6000
#define POST 300
#define CAP 8192
#define KSPLIT 6
#define KPART 768          // 4608 / 6

typedef unsigned long long ull;

// ---------------- scratch ----------------
__device__ float g_col[4608 * NPAD];            // im2col matrix [4608][2560]
__device__ float g_part[KSPLIT][512 * NPAD];    // split-K partials
__device__ float g_feat[512 * NPAD];            // conv output (bias+leaky)
__device__ float4 g_boxes[NANCH];
__device__ unsigned int g_key32[NANCH];
__device__ unsigned int g_hist[65536];
__device__ unsigned int g_cut;
__device__ unsigned int g_cnt;
__device__ ull g_sel[CAP];

// ---------------- f32x2 helpers ----------------
__device__ __forceinline__ void fma2(ull& d, ull a, ull b) {
    asm("fma.rn.f32x2 %0, %1, %2, %0;" : "+l"(d) : "l"(a), "l"(b));
}
__device__ __forceinline__ ull splat2(float x) {
    ull r;
    unsigned u = __float_as_uint(x);
    asm("mov.b64 %0, {%1, %1};" : "=l"(r) : "r"(u));
    return r;
}

// ---------------- zero histogram ----------------
__global__ void zero_hist_kernel() {
    g_hist[blockIdx.x * 256 + threadIdx.x] = 0u;
}

// ---------------- im2col: g_col[k][n] ----------------
__global__ __launch_bounds__(256) void im2col_kernel(const float* __restrict__ in) {
    int n = blockIdx.x * 256 + threadIdx.x;     // 0..2559
    int k = blockIdx.y;                          // 0..4607
    if (n >= NPAD) return;
    float v = 0.f;
    if (n < NPOS) {
        int ci = k / 9;
        int r = k - ci * 9;
        int kh = r / 3;
        int kw = r - kh * 3;
        int h = n / 50;
        int w = n - h * 50;
        int ih = h + kh - 1;
        int iw = w + kw - 1;
        if (ih >= 0 && ih < 50 && iw >= 0 && iw < 50)
            v = in[ci * NPOS + ih * 50 + iw];
    }
    g_col[(size_t)k * NPAD + n] = v;
}

// ---------------- conv GEMM: split-K, 128x64 tiles, f32x2 ----------------
// grid (40, 4, 6), 128 threads. thread tile 8(M) x 8(N) -> 8 x 4 f32x2 accs.
__global__ __launch_bounds__(128) void conv_gemm_kernel(const float* __restrict__ W) {
    __shared__ float As[2][16][128];
    __shared__ float Bs[2][16][64];
    const int bn = blockIdx.x * 64;
    const int bm = blockIdx.y * 128;
    const int kb = blockIdx.z * KPART;
    const int t = threadIdx.x;
    const int tm = t >> 3;    // 0..15
    const int tn = t & 7;     // 0..7

    ull acc[8][4];
#pragma unroll
    for (int i = 0; i < 8; i++)
#pragma unroll
        for (int j = 0; j < 4; j++) acc[i][j] = 0ull;

    const float* wrow = W + (size_t)(bm + t) * 4608 + kb;     // thread owns A row t
    const int bkl = t >> 3;            // B: row within tile (0..15)
    const int bnc = (t & 7) * 8;       // B: col group

    // prologue: load tile 0
    float4 a0 = *(const float4*)&wrow[0];
    float4 a1 = *(const float4*)&wrow[4];
    float4 a2 = *(const float4*)&wrow[8];
    float4 a3 = *(const float4*)&wrow[12];
    float4 b0 = *(const float4*)&g_col[(size_t)(kb + bkl) * NPAD + bn + bnc];
    float4 b1 = *(const float4*)&g_col[(size_t)(kb + bkl) * NPAD + bn + bnc + 4];
    {
        As[0][0][t] = a0.x;  As[0][1][t] = a0.y;  As[0][2][t] = a0.z;  As[0][3][t] = a0.w;
        As[0][4][t] = a1.x;  As[0][5][t] = a1.y;  As[0][6][t] = a1.z;  As[0][7][t] = a1.w;
        As[0][8][t] = a2.x;  As[0][9][t] = a2.y;  As[0][10][t] = a2.z; As[0][11][t] = a2.w;
        As[0][12][t] = a3.x; As[0][13][t] = a3.y; As[0][14][t] = a3.z; As[0][15][t] = a3.w;
        *(float4*)&Bs[0][bkl][bnc] = b0;
        *(float4*)&Bs[0][bkl][bnc + 4] = b1;
    }
    __syncthreads();

    int cur = 0;
    for (int it = 0; it < KPART / 16; it++) {
        int nxt = cur ^ 1;
        bool more = (it + 1) < KPART / 16;
        if (more) {
            int k0 = kb + (it + 1) * 16;
            a0 = *(const float4*)&wrow[(it + 1) * 16];
            a1 = *(const float4*)&wrow[(it + 1) * 16 + 4];
            a2 = *(const float4*)&wrow[(it + 1) * 16 + 8];
            a3 = *(const float4*)&wrow[(it + 1) * 16 + 12];
            b0 = *(const float4*)&g_col[(size_t)(k0 + bkl) * NPAD + bn + bnc];
            b1 = *(const float4*)&g_col[(size_t)(k0 + bkl) * NPAD + bn + bnc + 4];
        }
#pragma unroll
        for (int kk = 0; kk < 16; kk++) {
            float4 af0 = *(const float4*)&As[cur][kk][tm * 8];
            float4 af1 = *(const float4*)&As[cur][kk][tm * 8 + 4];
            ull bb0 = *(const ull*)&Bs[cur][kk][tn * 8];
            ull bb1 = *(const ull*)&Bs[cur][kk][tn * 8 + 2];
            ull bb2 = *(const ull*)&Bs[cur][kk][tn * 8 + 4];
            ull bb3 = *(const ull*)&Bs[cur][kk][tn * 8 + 6];
            ull aa[8];
            aa[0] = splat2(af0.x); aa[1] = splat2(af0.y);
            aa[2] = splat2(af0.z); aa[3] = splat2(af0.w);
            aa[4] = splat2(af1.x); aa[5] = splat2(af1.y);
            aa[6] = splat2(af1.z); aa[7] = splat2(af1.w);
#pragma unroll
            for (int i = 0; i < 8; i++) {
                fma2(acc[i][0], aa[i], bb0);
                fma2(acc[i][1], aa[i], bb1);
                fma2(acc[i][2], aa[i], bb2);
                fma2(acc[i][3], aa[i], bb3);
            }
        }
        if (more) {
            As[nxt][0][t] = a0.x;  As[nxt][1][t] = a0.y;  As[nxt][2][t] = a0.z;  As[nxt][3][t] = a0.w;
            As[nxt][4][t] = a1.x;  As[nxt][5][t] = a1.y;  As[nxt][6][t] = a1.z;  As[nxt][7][t] = a1.w;
            As[nxt][8][t] = a2.x;  As[nxt][9][t] = a2.y;  As[nxt][10][t] = a2.z; As[nxt][11][t] = a2.w;
            As[nxt][12][t] = a3.x; As[nxt][13][t] = a3.y; As[nxt][14][t] = a3.z; As[nxt][15][t] = a3.w;
            *(float4*)&Bs[nxt][bkl][bnc] = b0;
            *(float4*)&Bs[nxt][bkl][bnc + 4] = b1;
        }
        __syncthreads();
        cur = nxt;
    }

    float* dst = &g_part[blockIdx.z][(size_t)(bm + tm * 8) * NPAD + bn + tn * 8];
#pragma unroll
    for (int i = 0; i < 8; i++) {
        *(ull*)&dst[(size_t)i * NPAD]     = acc[i][0];
        *(ull*)&dst[(size_t)i * NPAD + 2] = acc[i][1];
        *(ull*)&dst[(size_t)i * NPAD + 4] = acc[i][2];
        *(ull*)&dst[(size_t)i * NPAD + 6] = acc[i][3];
    }
}

// ---------------- reduce split-K + bias + leaky ----------------
__global__ __launch_bounds__(256) void reduce_kernel(const float* __restrict__ bias) {
    int n = blockIdx.x * 256 + threadIdx.x;
    int m = blockIdx.y;
    size_t off = (size_t)m * NPAD + n;
    float v = g_part[0][off];
    v += g_part[1][off];
    v += g_part[2][off];
    v += g_part[3][off];
    v += g_part[4][off];
    v += g_part[5][off];
    v += bias[m];
    g_feat[off] = (v >= 0.f) ? v : 0.01f * v;
}

// ---------------- head GEMM (54x2560x512) fused with decode ----------------
// grid 40, 256 threads, BM=64(54), BN=64, BK=16, thread tile 4x4.
__global__ __launch_bounds__(256) void head_decode_kernel(const float* __restrict__ reg_w,
                                                          const float* __restrict__ cls_w,
                                                          const float* __restrict__ reg_b,
                                                          const float* __restrict__ cls_b) {
    __shared__ float As[16][64];
    __shared__ float Bs[16][64];
    __shared__ float Psm[54][65];
    const int bn = blockIdx.x * 64;
    const int t = threadIdx.x;
    float acc[4][4];
#pragma unroll
    for (int i = 0; i < 4; i++)
#pragma unroll
        for (int j = 0; j < 4; j++) acc[i][j] = 0.f;

    const int tm = t >> 4, tn = t & 15;

    for (int k0 = 0; k0 < 512; k0 += 16) {
        {
            int m = t >> 2;
            int kq = (t & 3) * 4;
            float4 v = make_float4(0.f, 0.f, 0.f, 0.f);
            if (m < 36) v = *(const float4*)&reg_w[m * 512 + k0 + kq];
            else if (m < 54) v = *(const float4*)&cls_w[(m - 36) * 512 + k0 + kq];
            As[kq + 0][m] = v.x;
            As[kq + 1][m] = v.y;
            As[kq + 2][m] = v.z;
            As[kq + 3][m] = v.w;
        }
        {
            int kl = t >> 4;
            int nq = (t & 15) * 4;
            *(float4*)&Bs[kl][nq] = *(const float4*)&g_feat[(size_t)(k0 + kl) * NPAD + bn + nq];
        }
        __syncthreads();
#pragma unroll
        for (int kk = 0; kk < 16; kk++) {
            float a[4], b[4];
            *(float4*)&a[0] = *(float4*)&As[kk][tm * 4];
            *(float4*)&b[0] = *(float4*)&Bs[kk][tn * 4];
#pragma unroll
            for (int i = 0; i < 4; i++)
#pragma unroll
                for (int j = 0; j < 4; j++) acc[i][j] += a[i] * b[j];
        }
        __syncthreads();
    }
#pragma unroll
    for (int i = 0; i < 4; i++) {
        int m = tm * 4 + i;
        if (m < 54)
#pragma unroll
            for (int j = 0; j < 4; j++) Psm[m][tn * 4 + j] = acc[i][j];
    }
    __syncthreads();

    // decode: 64 positions x 9 anchors = 576 candidates
    for (int c = t; c < 576; c += 256) {
        int pl = c / 9;
        int a = c - pl * 9;
        int pos = bn + pl;
        if (pos >= NPOS) continue;
        int h = pos / 50;
        int w = pos - h * 50;

        float pr0 = Psm[4 * a + 0][pl] + reg_b[4 * a + 0];
        float pr1 = Psm[4 * a + 1][pl] + reg_b[4 * a + 1];
        float pr2 = Psm[4 * a + 2][pl] + reg_b[4 * a + 2];
        float pr3 = Psm[4 * a + 3][pl] + reg_b[4 * a + 3];
        float l0 = Psm[36 + 2 * a + 0][pl] + cls_b[2 * a + 0];
        float l1 = Psm[36 + 2 * a + 1][pl] + cls_b[2 * a + 1];

        float mx = fmaxf(l0, l1);
        float e0 = expf(l0 - mx);
        float e1 = expf(l1 - mx);
        float score = e1 / (e0 + e1);

        const float rs_[3] = {0.5f, 1.0f, 2.0f};
        const float ss_[3] = {8.0f, 16.0f, 32.0f};
        int ri = a / 3;
        int si = a - ri * 3;
        float hs = (16.0f * ss_[si]) * sqrtf(rs_[ri]);
        float ws = (16.0f * ss_[si]) * sqrtf(1.0f / rs_[ri]);
        float cx = 16.0f * (float)h + 8.0f;
        float cy = 16.0f * (float)w + 8.0f;
        float ax1 = cx - ws * 0.5f;
        float ay1 = cy - hs * 0.5f;

        const float hi = 799.0f;
        float rx1 = fminf(fmaxf(pr0 + ax1, 0.f), hi);
        float ry1 = fminf(fmaxf(pr1 + ay1, 0.f), hi);
        float rx2 = fminf(fmaxf(pr0 + ax1 + pr2 + ws, 0.f), hi);
        float ry2 = fminf(fmaxf(pr1 + ay1 + pr3 + hs, 0.f), hi);

        float wv = pr2 + ws;
        float hv = pr3 + hs;
        bool valid = (wv >= 16.0f) && (hv >= 16.0f);
        float s = valid ? score : -INFINITY;

        int idx = pos * 9 + a;
        g_boxes[idx] = make_float4(rx1, ry1, rx2, ry2);

        unsigned u = __float_as_uint(s);
        u = (u & 0x80000000u) ? ~u : (u | 0x80000000u);
        unsigned du = ~u;                // ascending key == descending score
        g_key32[idx] = du;
        atomicAdd(&g_hist[du >> 16], 1u);
    }
}

// ---------------- select cutoff bin (single block) ----------------
__global__ __launch_bounds__(1024) void select_kernel() {
    __shared__ unsigned int ps[1024];
    const int t = threadIdx.x;
    unsigned int s = 0;
    int base = t * 64;
#pragma unroll 8
    for (int b = 0; b < 64; b++) s += g_hist[base + b];
    ps[t] = s;
    __syncthreads();
    for (int off = 1; off < 1024; off <<= 1) {
        unsigned int v = (t >= off) ? ps[t - off] : 0u;
        __syncthreads();
        ps[t] += v;
        __syncthreads();
    }
    unsigned int excl = ps[t] - s;
    if (excl < PRE && ps[t] >= PRE) {
        unsigned int c = excl;
        for (int b = 0; b < 64; b++) {
            c += g_hist[base + b];
            if (c >= PRE) { g_cut = (unsigned)(base + b); break; }
        }
    }
    if (t == 0) g_cnt = 0u;
    // prefill selection buffer with +inf keys
    for (int i = t; i < CAP; i += 1024) g_sel[i] = 0xFFFFFFFFFFFFFFFFull;
}

// ---------------- compact candidates <= cutoff ----------------
__global__ __launch_bounds__(256) void compact_kernel() {
    int i = blockIdx.x * 256 + threadIdx.x;
    if (i >= NANCH) return;
    unsigned int k = g_key32[i];
    if ((k >> 16) <= g_cut) {
        unsigned int p = atomicAdd(&g_cnt, 1u);
        if (p < CAP) g_sel[p] = ((ull)k << 32) | (unsigned)i;
    }
}

// ---------------- fused sort (8192 bitonic) + NMS + output ----------------
extern __shared__ char snms[];
__global__ __launch_bounds__(1024) void sortnms_kernel(float* __restrict__ out) {
    ull* s = (ull*)snms;                               // 8192 * 8 = 64KB
    float* X1 = (float*)(snms + CAP * 8);              // 5 * 6000 * 4 = 120KB
    float* Y1 = X1 + PRE;
    float* X2 = Y1 + PRE;
    float* Y2 = X2 + PRE;
    float* AR = Y2 + PRE;
    unsigned char* keep = (unsigned char*)(AR + PRE);  // 6000B
    int* sel = (int*)(snms + CAP * 8 + 5 * PRE * 4 + 6016);
    __shared__ int s_cur, s_cnt;
    const int t = threadIdx.x;

    for (int i = t; i < CAP; i += 1024) s[i] = g_sel[i];
    __syncthreads();

    // bitonic sort ascending, 8192 elements
    for (int k = 2; k <= CAP; k <<= 1) {
        for (int j = k >> 1; j > 0; j >>= 1) {
#pragma unroll
            for (int p = 0; p < 4; p++) {
                int q = t + p * 1024;
                int i = ((q & ~(j - 1)) << 1) | (q & (j - 1));
                int pp = i | j;
                bool up = ((i & k) == 0);
                ull a = s[i], b = s[pp];
                bool sw = up ? (a > b) : (a < b);
                if (sw) { s[i] = b; s[pp] = a; }
            }
            __syncthreads();
        }
    }

    // load top-6000 boxes
    for (int r = t; r < PRE; r += 1024) {
        int idx = (int)(s[r] & 0xFFFFFFFFull);
        float4 b = g_boxes[idx];
        X1[r] = b.x; Y1[r] = b.y; X2[r] = b.z; Y2[r] = b.w;
        AR[r] = (b.z - b.x + 1.0f) * (b.w - b.y + 1.0f);
        keep[r] = 1;
    }
    if (t == 0) s_cnt = 0;
    __syncthreads();

    int i_scan = 0;  // thread 0 only
    while (true) {
        if (t == 0) {
            int i = i_scan;
            while (i < PRE && !keep[i]) i++;
            if (i < PRE && s_cnt < POST) {
                sel[s_cnt] = i;
                s_cnt++;
                s_cur = i;
                i_scan = i + 1;
            } else {
                s_cur = -1;
            }
        }
        __syncthreads();
        int cur = s_cur;
        if (cur < 0) break;
        float x1i = X1[cur], y1i = Y1[cur], x2i = X2[cur], y2i = Y2[cur], ai = AR[cur];
        for (int j = cur + 1 + t; j < PRE; j += 1024) {
            float xx1 = fmaxf(x1i, X1[j]);
            float yy1 = fmaxf(y1i, Y1[j]);
            float xx2 = fminf(x2i, X2[j]);
            float yy2 = fmaxf(y2i, Y2[j]);   // reference's maximum bug preserved
            float w = fmaxf(0.f, xx2 - xx1 + 1.0f);
            float h = fmaxf(0.f, yy2 - yy1 + 1.0f);
            float inter = w * h;
            float ov = inter / (ai + AR[j] - inter);
            if (ov > 0.7f) keep[j] = 0;
        }
        __syncthreads();
    }

    if (t == 0) {
        int c = s_cnt;
        for (int i = 0; i < PRE && c < POST; i++)
            if (!keep[i]) sel[c++] = i;
        s_cnt = c;
    }
    __syncthreads();

    if (t < POST) {
        int idx = sel[t];
        out[t * 4 + 0] = X1[idx];
        out[t * 4 + 1] = Y1[idx];
        out[t * 4 + 2] = X2[idx] - X1[idx] + 1.0f;
        out[t * 4 + 3] = Y2[idx] - Y1[idx] + 1.0f;
    }
}

// ---------------- launch ----------------
extern "C" void kernel_launch(void* const* d_in, const int* in_sizes, int n_in,
                              void* d_out, int out_size) {
    const float* in_features = (const float*)d_in[0];
    const float* conv_w = (const float*)d_in[1];
    const float* conv_b = (const float*)d_in[2];
    const float* reg_w = (const float*)d_in[3];
    const float* reg_b = (const float*)d_in[4];
    const float* cls_w = (const float*)d_in[5];
    const float* cls_b = (const float*)d_in[6];
    float* out = (float*)d_out;

    const float* in7 = in_features + (size_t)7 * 512 * NPOS;  // only batch -1 consumed

    zero_hist_kernel<<<256, 256>>>();
    im2col_kernel<<<dim3(10, 4608), 256>>>(in7);
    conv_gemm_kernel<<<dim3(40, 4, KSPLIT), 128>>>(conv_w);
    reduce_kernel<<<dim3(10, 512), 256>>>(conv_b);
    head_decode_kernel<<<40, 256>>>(reg_w, cls_w, reg_b, cls_b);
    select_kernel<<<1, 1024>>>();
    compact_kernel<<<88, 256>>>();

    const int smem_bytes = CAP * 8 + 5 * PRE * 4 + 6016 + POST * 4 + 64;
    cudaFuncSetAttribute(sortnms_kernel, cudaFuncAttributeMaxDynamicSharedMemorySize, smem_bytes);
    sortnms_kernel<<<1, 1024, smem_bytes>>>(out);
}